// round 2
// baseline (speedup 1.0000x reference)
#include <cuda_runtime.h>

// SoftRank: out[b,j,c] = (1/N) * sum_i sigmoid(ALPHA*(x[b,j,c]-x[b,i,c]))
// ALPHA=1000 -> sigmoid saturates outside |d| <= W. Sort each (b,c) column,
// count saturated-1 contributions via rank, evaluate only the window exactly.

#define ALPHA   1000.0f
#define WINDOW  0.033f   // ALPHA*W = 33 -> tail err exp(-33) ~ 4.7e-15 per term
#define NN      1024
#define CC      16
#define BB      8

__global__ __launch_bounds__(NN) void softrank_sorted_kernel(
    const float* __restrict__ x, float* __restrict__ out)
{
    const int b = blockIdx.x >> 4;       // blockIdx.x / CC
    const int c = blockIdx.x & (CC - 1); // blockIdx.x % CC

    __shared__ float s[NN];              // sorted copy

    const int t = threadIdx.x;
    // Column (b, :, c): stride CC floats.
    const float v = x[(b * NN + t) * CC + c];
    s[t] = v;
    __syncthreads();

    // Bitonic sort ascending, 1024 threads, each pair handled by the lower index.
    #pragma unroll 1
    for (int k = 2; k <= NN; k <<= 1) {
        #pragma unroll 1
        for (int j = k >> 1; j > 0; j >>= 1) {
            const int ixj = t ^ j;
            if (ixj > t) {
                const bool up = ((t & k) == 0);
                const float a  = s[t];
                const float bb = s[ixj];
                if ((a > bb) == up) { s[t] = bb; s[ixj] = a; }
            }
            __syncthreads();
        }
    }

    // For this thread's ORIGINAL element v:
    //   lower = #elements with s[i] <  v - W  -> each contributes exactly 1 (to 5e-15)
    //   window [lower, upper): evaluate sigmoid exactly
    //   above v + W: contributes 0
    const float loVal = v - WINDOW;
    const float hiVal = v + WINDOW;

    int lo = 0, hi = NN;
    while (lo < hi) {                    // first idx with s[m] >= loVal
        const int m = (lo + hi) >> 1;
        if (s[m] < loVal) lo = m + 1; else hi = m;
    }
    const int lower = lo;

    hi = NN;                             // first idx with s[m] > hiVal
    while (lo < hi) {
        const int m = (lo + hi) >> 1;
        if (s[m] <= hiVal) lo = m + 1; else hi = m;
    }
    const int upper = lo;

    float sum = (float)lower;
    for (int i = lower; i < upper; ++i) {
        const float d = ALPHA * (v - s[i]);
        sum += 1.0f / (1.0f + __expf(-d));
    }

    out[(b * NN + t) * CC + c] = sum * (1.0f / (float)NN);
}

extern "C" void kernel_launch(void* const* d_in, const int* in_sizes, int n_in,
                              void* d_out, int out_size)
{
    const float* x = (const float*)d_in[0];
    float* out = (float*)d_out;
    softrank_sorted_kernel<<<BB * CC, NN>>>(x, out);
}

// round 3
// speedup vs baseline: 1.5748x; 1.5748x over previous
#include <cuda_runtime.h>

// SoftRank: out[b,j,c] = (1/N) * sum_i sigmoid(ALPHA*(x[b,j,c]-x[b,i,c]))
// ALPHA=1000 -> sigmoid saturates fast. Per (b,c) column:
//   hybrid register/shuffle+smem bitonic sort carrying original index,
//   rank = sorted position (free), exact sigmoid only for |arg|<=9 window
//   via MUFU.TANH.

#define HALF_ALPHA 500.0f
#define WINDOW     0.009f   // arg <= 9 -> tail err ~1.2e-4 per edge, /N after
#define NN         1024
#define CC         16
#define BB         8

__device__ __forceinline__ float fast_tanh(float x) {
    float r;
    asm("tanh.approx.f32 %0, %1;" : "=f"(r) : "f"(x));
    return r;
}

__global__ __launch_bounds__(NN) void softrank_kernel(
    const float* __restrict__ x, float* __restrict__ out)
{
    const int b = blockIdx.x >> 4;       // / CC
    const int c = blockIdx.x & (CC - 1); // % CC

    __shared__ uint2 sp[NN];             // {value bits, payload} for cross-warp passes
    __shared__ float sk[NN];             // final sorted keys for the epilogue scan

    const int t    = threadIdx.x;
    const int lane = t & 31;

    float    k = x[(b * NN + t) * CC + c];
    unsigned p = (unsigned)t;            // original row index rides along

    // ---- bitonic sort: intra-warp stages (kk = 2..32), register + shfl only ----
    #pragma unroll
    for (int kk = 2; kk <= 32; kk <<= 1) {
        #pragma unroll
        for (int j = kk >> 1; j >= 1; j >>= 1) {
            float    k2 = __shfl_xor_sync(0xffffffffu, k, j);
            unsigned p2 = __shfl_xor_sync(0xffffffffu, p, j);
            const bool up      = ((t & kk) == 0);
            const bool low     = ((lane & j) == 0);
            const bool keepMin = (up == low);
            const bool take    = keepMin ? (k2 < k) : (k2 > k);
            if (take) { k = k2; p = p2; }
        }
    }

    // ---- cross-warp merge stages (kk = 64..1024) ----
    #pragma unroll 1
    for (int kk = 64; kk <= NN; kk <<= 1) {
        // strides j >= 32 go through shared memory
        #pragma unroll 1
        for (int j = kk >> 1; j >= 32; j >>= 1) {
            __syncthreads();                       // prior reads done before rewrite
            sp[t] = make_uint2(__float_as_uint(k), p);
            __syncthreads();
            const uint2 o  = sp[t ^ j];
            const float k2 = __uint_as_float(o.x);
            const bool up      = ((t & kk) == 0);
            const bool low     = ((t & j) == 0);
            const bool keepMin = (up == low);
            const bool take    = keepMin ? (k2 < k) : (k2 > k);
            if (take) { k = k2; p = o.y; }
        }
        // strides j <= 16 back to shuffles, no barriers
        #pragma unroll
        for (int j = 16; j >= 1; j >>= 1) {
            float    k2 = __shfl_xor_sync(0xffffffffu, k, j);
            unsigned p2 = __shfl_xor_sync(0xffffffffu, p, j);
            const bool up      = ((t & kk) == 0);
            const bool low     = ((lane & j) == 0);
            const bool keepMin = (up == low);
            const bool take    = keepMin ? (k2 < k) : (k2 > k);
            if (take) { k = k2; p = p2; }
        }
    }

    // ---- epilogue: thread t holds the t-th smallest value (rank = t) ----
    __syncthreads();
    sk[t] = k;
    __syncthreads();

    const float loVal = k - WINDOW;
    const float hiVal = k + WINDOW;

    float sumT = 0.0f;   // sum of tanh terms
    int   cntD = 0;      // in-window neighbors below
    int   cntU = 0;      // in-window neighbors above

    for (int i = t - 1; i >= 0; --i) {           // coalesced, conflict-free LDS
        const float si = sk[i];
        if (si < loVal) break;
        sumT += fast_tanh(HALF_ALPHA * (k - si));
        ++cntD;
    }
    for (int i = t + 1; i < NN; ++i) {
        const float si = sk[i];
        if (si > hiVal) break;
        sumT += fast_tanh(HALF_ALPHA * (k - si));
        ++cntU;
    }

    // exact below-window count contributes 1 each; window terms 0.5 + 0.5*tanh;
    // self term is exactly 0.5
    const float res = (float)(t - cntD)
                    + 0.5f * (float)(cntD + cntU + 1)
                    + 0.5f * sumT;

    out[(b * NN + p) * CC + c] = res * (1.0f / (float)NN);
}

extern "C" void kernel_launch(void* const* d_in, const int* in_sizes, int n_in,
                              void* d_out, int out_size)
{
    const float* x = (const float*)d_in[0];
    float* out = (float*)d_out;
    softrank_kernel<<<BB * CC, NN>>>(x, out);
}

// round 4
// speedup vs baseline: 2.3077x; 1.4654x over previous
#include <cuda_runtime.h>

// SoftRank via bucket-histogram rank + windowed exact sigmoid.
// out[b,j,c] = (1/N) * sum_i sigmoid(1000*(x[b,j,c]-x[b,i,c]))
//
// Per (b,c) column: histogram into 4096 buckets, exclusive prefix sum,
// scatter into bucket order. Then for element v:
//   result = prefix[bucket(v-W)]                 (all strictly-lower buckets -> 1 each)
//          + sum over scanned region of (0.5 + 0.5*tanh(500*(v-s)))
// tanh.approx saturates to +/-1, so the scan body is branchless and exact
// (to tanh-approx precision) for every scanned element.

#define NN       1024
#define CC       16
#define BB       8
#define NBKT     4096
#define RANGE_LO (-5.0f)
#define INV_W    409.6f          // NBKT / 10.0
#define WINDOW   0.009f          // |alpha*(v-s)| <= 9 outside -> tail ~1.2e-4

__device__ __forceinline__ float fast_tanh(float x) {
    float r;
    asm("tanh.approx.f32 %0, %1;" : "=f"(r) : "f"(x));
    return r;
}

__device__ __forceinline__ int bucket_of(float v) {
    int b = (int)((v - RANGE_LO) * INV_W);
    return min(max(b, 0), NBKT - 1);
}

__global__ __launch_bounds__(NN) void softrank_bucket_kernel(
    const float* __restrict__ x, float* __restrict__ out)
{
    const int b = blockIdx.x >> 4;       // / CC
    const int c = blockIdx.x & (CC - 1); // % CC

    __shared__ unsigned cnt[NBKT];       // counts -> exclusive prefix (in place)
    __shared__ float    skey[NN];        // values in bucket order
    __shared__ unsigned wsum[32];        // per-warp scan totals

    const int t    = threadIdx.x;
    const int lane = t & 31;
    const int wid  = t >> 5;

    // ---- zero counts (uint4, 4 buckets per thread) ----
    ((uint4*)cnt)[t] = make_uint4(0u, 0u, 0u, 0u);

    const float v  = x[(b * NN + t) * CC + c];
    const int   bk = bucket_of(v);

    __syncthreads();

    // ---- histogram; remember slot within bucket ----
    const unsigned slot = atomicAdd(&cnt[bk], 1u);
    __syncthreads();

    // ---- exclusive prefix sum over 4096 counts (4 per thread) ----
    const uint4 c4 = ((uint4*)cnt)[t];
    const unsigned tsum = c4.x + c4.y + c4.z + c4.w;

    // warp-inclusive scan of per-thread sums
    unsigned inc = tsum;
    #pragma unroll
    for (int j = 1; j < 32; j <<= 1) {
        unsigned n = __shfl_up_sync(0xffffffffu, inc, j);
        if (lane >= j) inc += n;
    }
    if (lane == 31) wsum[wid] = inc;
    __syncthreads();

    if (wid == 0) {
        unsigned w = wsum[lane];
        unsigned wi = w;
        #pragma unroll
        for (int j = 1; j < 32; j <<= 1) {
            unsigned n = __shfl_up_sync(0xffffffffu, wi, j);
            if (lane >= j) wi += n;
        }
        wsum[lane] = wi - w;             // exclusive warp offset
    }
    __syncthreads();

    const unsigned texcl = wsum[wid] + (inc - tsum);  // exclusive prefix, this thread's 4
    uint4 p4;
    p4.x = texcl;
    p4.y = texcl + c4.x;
    p4.z = texcl + c4.x + c4.y;
    p4.w = texcl + c4.x + c4.y + c4.z;
    ((uint4*)cnt)[t] = p4;               // cnt[] now holds exclusive prefix
    __syncthreads();

    // ---- scatter value into bucket order ----
    skey[cnt[bk] + slot] = v;
    __syncthreads();

    // ---- windowed evaluation ----
    const int b_lo = bucket_of(v - WINDOW);
    const int b_hi = bucket_of(v + WINDOW);

    const unsigned start = cnt[b_lo];
    const unsigned end   = (b_hi + 1 >= NBKT) ? (unsigned)NN : cnt[b_hi + 1];

    const float a = 500.0f * v;          // tanh arg = a - 500*s
    float sum = (float)start;            // all lower buckets contribute 1 each
    for (unsigned i = start; i < end; ++i) {
        const float th = fast_tanh(fmaf(-500.0f, skey[i], a));
        sum = fmaf(0.5f, th, sum + 0.5f);
    }

    out[(b * NN + t) * CC + c] = sum * (1.0f / (float)NN);
}

extern "C" void kernel_launch(void* const* d_in, const int* in_sizes, int n_in,
                              void* d_out, int out_size)
{
    const float* x = (const float*)d_in[0];
    float* out = (float*)d_out;
    softrank_bucket_kernel<<<BB * CC, NN>>>(x, out);
}